// round 4
// baseline (speedup 1.0000x reference)
#include <cuda_runtime.h>
#include <cstdint>

// ============================================================================
// SpectralNetLoss:
//   2n·loss = Σ_ij W_ij (sq_i + sq_j)  −  2 Σ_ij W_ij (y_i · y_j)
// Term 1: per-element FFMA on W fragments (no GEMM needed).
// Term 2: tf32 mma.sync GEMM  U = W (8192x8192) × Yt (8192x64), folded with Y.
// No tcgen05 (compute_103 base target); cp.async + HMMA.1688.F32.TF32.
// ============================================================================

#define N_DIM     8192
#define KF        64
#define M_TILE    128
#define KCHUNK    32
#define KSPLIT    8
#define K_RANGE   (N_DIM / KSPLIT)        // 1024
#define NITER     (K_RANGE / KCHUNK)      // 32
#define RS        36                      // padded row stride in floats (32 + 4)

#define A_FLOATS  (M_TILE * RS)           // 4608
#define B_FLOATS  (KF * RS)               // 2304
#define SQ_FLOATS 32
#define STAGE_FLOATS (A_FLOATS + B_FLOATS + SQ_FLOATS)   // 6944
#define STAGE_BYTES  (STAGE_FLOATS * 4)                  // 27776
#define SMEM_BYTES   (2 * STAGE_BYTES)                   // 55552

// Y transposed [64][8192] and per-row squared norms, built by prep kernel.
__device__ float g_Yt[(size_t)KF * N_DIM];
__device__ float g_sq[N_DIM];

// ---------------------------------------------------------------- helpers
__device__ __forceinline__ uint32_t smem_u32(const void* p) {
    uint32_t a;
    asm("{ .reg .u64 t; cvta.to.shared.u64 t, %1; cvt.u32.u64 %0, t; }"
        : "=r"(a) : "l"(p));
    return a;
}
__device__ __forceinline__ void cp_async16(uint32_t dst, const void* src) {
    asm volatile("cp.async.cg.shared.global [%0], [%1], 16;"
                 :: "r"(dst), "l"(src));
}
__device__ __forceinline__ void cp_commit() {
    asm volatile("cp.async.commit_group;" ::: "memory");
}
__device__ __forceinline__ void cp_wait1() {
    asm volatile("cp.async.wait_group 1;" ::: "memory");
}
__device__ __forceinline__ void cp_wait0() {
    asm volatile("cp.async.wait_group 0;" ::: "memory");
}
__device__ __forceinline__ void mma_tf32(float* c, const uint32_t* a,
                                         const uint32_t* b) {
    asm volatile(
        "mma.sync.aligned.m16n8k8.row.col.f32.tf32.tf32.f32 "
        "{%0,%1,%2,%3}, {%4,%5,%6,%7}, {%8,%9}, {%0,%1,%2,%3};"
        : "+f"(c[0]), "+f"(c[1]), "+f"(c[2]), "+f"(c[3])
        : "r"(a[0]), "r"(a[1]), "r"(a[2]), "r"(a[3]), "r"(b[0]), "r"(b[1]));
}

// ---------------------------------------------------------------- prep
__global__ void spec_prep(const float* __restrict__ Y, float* __restrict__ out) {
    int j = blockIdx.x * blockDim.x + threadIdx.x;
    if (j == 0) out[0] = 0.0f;
    if (j >= N_DIM) return;
    const float4* yp = (const float4*)(Y + (size_t)j * KF);
    float sq = 0.0f;
#pragma unroll
    for (int q = 0; q < 16; q++) {
        float4 y = yp[q];
        sq += y.x * y.x + y.y * y.y + y.z * y.z + y.w * y.w;
        g_Yt[(size_t)(4 * q + 0) * N_DIM + j] = y.x;
        g_Yt[(size_t)(4 * q + 1) * N_DIM + j] = y.y;
        g_Yt[(size_t)(4 * q + 2) * N_DIM + j] = y.z;
        g_Yt[(size_t)(4 * q + 3) * N_DIM + j] = y.w;
    }
    g_sq[j] = sq;
}

// ---------------------------------------------------------------- loader
__device__ __forceinline__ void load_chunk(uint32_t sbase, const float* wp,
                                           const float* yp, const float* sp,
                                           int tid) {
#pragma unroll
    for (int u = 0; u < 13; u++) {
        int idx = tid + u * 128;
        if (idx < 1024) {                         // A: 128 rows x 8 float4
            int r = idx >> 3, sg = idx & 7;
            cp_async16(sbase + (uint32_t)(r * RS + sg * 4) * 4,
                       wp + (size_t)r * N_DIM + sg * 4);
        } else if (idx < 1536) {                  // B: 64 rows x 8 float4
            int q = idx - 1024;
            int r = q >> 3, sg = q & 7;
            cp_async16(sbase + (uint32_t)(A_FLOATS + r * RS + sg * 4) * 4,
                       yp + (size_t)r * N_DIM + sg * 4);
        } else if (idx < 1544) {                  // col sq: 32 floats
            int q = idx - 1536;
            cp_async16(sbase + (uint32_t)(A_FLOATS + B_FLOATS) * 4 + q * 16,
                       sp + q * 4);
        }
    }
    cp_commit();
}

// ---------------------------------------------------------------- main
__global__ void __launch_bounds__(128, 4)
spec_main(const float* __restrict__ W, const float* __restrict__ Y,
          float* __restrict__ out) {
    extern __shared__ float smem[];
    const uint32_t sb = smem_u32(smem);

    const int tid = threadIdx.x;
    const int w   = tid >> 5;          // warp 0..3
    const int lid = tid & 31;
    const int q   = lid & 3;           // k-lane within quad
    const int g   = lid >> 2;          // row/col group 0..7
    const int bx  = blockIdx.x;
    const int mtile = bx & 63;
    const int ks    = bx >> 6;
    const int m0    = mtile * M_TILE;
    const int kb    = ks * K_RANGE;
    const int w32   = w * 32;          // warp's row offset inside tile

    const float* wbase = W + (size_t)m0 * N_DIM + kb;
    const float* ybase = g_Yt + kb;
    const float* sbse  = g_sq + kb;

    // row squared-norms for this thread's 4 rows (fixed across k)
    float sqi[2][2];
#pragma unroll
    for (int mt = 0; mt < 2; mt++) {
        sqi[mt][0] = g_sq[m0 + w32 + mt * 16 + g];
        sqi[mt][1] = g_sq[m0 + w32 + mt * 16 + g + 8];
    }

    float acc[2][8][4];
#pragma unroll
    for (int mt = 0; mt < 2; mt++)
#pragma unroll
        for (int nt = 0; nt < 8; nt++)
#pragma unroll
            for (int v = 0; v < 4; v++) acc[mt][nt][v] = 0.0f;
    float scal = 0.0f;

    load_chunk(sb, wbase, ybase, sbse, tid);

    for (int j = 0; j < NITER; j++) {
        if (j + 1 < NITER) {
            load_chunk(sb + ((j + 1) & 1) * STAGE_BYTES,
                       wbase + (j + 1) * KCHUNK, ybase + (j + 1) * KCHUNK,
                       sbse + (j + 1) * KCHUNK, tid);
            cp_wait1();
        } else {
            cp_wait0();
        }
        __syncthreads();

        const float* As = smem + (j & 1) * STAGE_FLOATS;
        const float* Bs = As + A_FLOATS;
        const float* Ss = Bs + B_FLOATS;

#pragma unroll
        for (int kst = 0; kst < 4; kst++) {
            const int k0 = kst * 8;
            const float sq0 = Ss[k0 + q];
            const float sq1 = Ss[k0 + q + 4];
            uint32_t a[2][4];
#pragma unroll
            for (int mt = 0; mt < 2; mt++) {
                const float* ap = As + (w32 + mt * 16 + g) * RS + k0 + q;
                float a0 = ap[0];
                float a1 = ap[8 * RS];
                float a2 = ap[4];
                float a3 = ap[8 * RS + 4];
                scal += a0 * (sqi[mt][0] + sq0) + a2 * (sqi[mt][0] + sq1) +
                        a1 * (sqi[mt][1] + sq0) + a3 * (sqi[mt][1] + sq1);
                a[mt][0] = __float_as_uint(a0);
                a[mt][1] = __float_as_uint(a1);
                a[mt][2] = __float_as_uint(a2);
                a[mt][3] = __float_as_uint(a3);
            }
#pragma unroll
            for (int nt = 0; nt < 8; nt++) {
                const float* bp = Bs + (nt * 8 + g) * RS + k0 + q;
                uint32_t b[2];
                b[0] = __float_as_uint(bp[0]);
                b[1] = __float_as_uint(bp[4]);
                mma_tf32(acc[0][nt], a[0], b);
                mma_tf32(acc[1][nt], a[1], b);
            }
        }
        __syncthreads();
    }

    // ------------- epilogue: fold U with Y, reduce to scalar ---------------
    float dot = 0.0f;
#pragma unroll
    for (int mt = 0; mt < 2; mt++) {
        const int r0 = m0 + w32 + mt * 16 + g;
#pragma unroll
        for (int nt = 0; nt < 8; nt++) {
            const int c0 = nt * 8 + 2 * q;
            float2 y0 = *(const float2*)(Y + (size_t)r0 * KF + c0);
            float2 y1 = *(const float2*)(Y + (size_t)(r0 + 8) * KF + c0);
            dot += acc[mt][nt][0] * y0.x + acc[mt][nt][1] * y0.y +
                   acc[mt][nt][2] * y1.x + acc[mt][nt][3] * y1.y;
        }
    }
    float total = scal - 2.0f * dot;
#pragma unroll
    for (int o = 16; o; o >>= 1)
        total += __shfl_xor_sync(0xffffffffu, total, o);

    __syncthreads();                       // stages no longer needed
    if (lid == 0) smem[w] = total;
    __syncthreads();
    if (tid == 0) {
        atomicAdd(out, (smem[0] + smem[1] + smem[2] + smem[3]) *
                           (1.0f / (2.0f * (float)N_DIM)));
    }
}

// ---------------------------------------------------------------- launch
extern "C" void kernel_launch(void* const* d_in, const int* in_sizes, int n_in,
                              void* d_out, int out_size) {
    const float* W = (const float*)d_in[0];
    const float* Y = (const float*)d_in[1];
    float* out = (float*)d_out;

    cudaFuncSetAttribute(spec_main, cudaFuncAttributeMaxDynamicSharedMemorySize,
                         SMEM_BYTES);

    spec_prep<<<N_DIM / 256, 256>>>(Y, out);
    spec_main<<<64 * KSPLIT, 128, SMEM_BYTES>>>(W, Y, out);
}